// round 2
// baseline (speedup 1.0000x reference)
#include <cuda_runtime.h>
#include <math.h>

// Problem constants (fixed shapes)
#define T    2048
#define DM   1024
#define NE   8
#define FF   4096

// ---------------- scratch (static device globals; no allocation) ----------------
__device__ int   g_count[NE];
__device__ int   g_cursor[NE];
__device__ int   g_offset[NE];
__device__ int   g_topk_idx[T * 2];
__device__ float g_topk_w[T * 2];
__device__ int   g_tok[2 * T];     // compacted per-expert token lists
__device__ float g_wgt[2 * T];     // matching combine weights
__device__ float g_inter[(size_t)(2 * T) * FF];  // 4096 x 4096 fp32 = 64 MB

// ---------------- init: zero counters ----------------
__global__ void init_kernel() {
    int i = threadIdx.x;
    if (i < NE) { g_count[i] = 0; g_cursor[i] = 0; }
}

// ---------------- router: logits, softmax, top-2, counts ----------------
__global__ void router_kernel(const float* __restrict__ x,
                              const float* __restrict__ gw,
                              float* __restrict__ logits_out) {
    int t = blockIdx.x;
    int warp = threadIdx.x >> 5;
    int lane = threadIdx.x & 31;
    const float* xr = x + (size_t)t * DM;
    const float* gr = gw + (size_t)warp * DM;
    float s = 0.f;
    for (int j = lane; j < DM; j += 32) s += xr[j] * gr[j];
    #pragma unroll
    for (int o = 16; o > 0; o >>= 1) s += __shfl_xor_sync(0xFFFFFFFFu, s, o);

    __shared__ float lg[NE];
    if (lane == 0) lg[warp] = s;
    __syncthreads();

    if (threadIdx.x == 0) {
        float mx = lg[0];
        #pragma unroll
        for (int e = 1; e < NE; e++) mx = fmaxf(mx, lg[e]);
        float p[NE];
        #pragma unroll
        for (int e = 0; e < NE; e++) p[e] = expf(lg[e] - mx);
        // top-2 of softmax probabilities (monotone in logits); ties -> lowest index
        int i0 = 0;
        #pragma unroll
        for (int e = 1; e < NE; e++) if (p[e] > p[i0]) i0 = e;
        int i1 = -1;
        #pragma unroll
        for (int e = 0; e < NE; e++) {
            if (e == i0) continue;
            if (i1 < 0 || p[e] > p[i1]) i1 = e;
        }
        float inv = 1.f / (p[i0] + p[i1]);
        float w0 = p[i0] * inv, w1 = p[i1] * inv;
        g_topk_idx[t * 2 + 0] = i0;
        g_topk_idx[t * 2 + 1] = i1;
        g_topk_w[t * 2 + 0] = w0;
        g_topk_w[t * 2 + 1] = w1;
        atomicAdd(&g_count[i0], 1);
        atomicAdd(&g_count[i1], 1);
        #pragma unroll
        for (int e = 0; e < NE; e++) logits_out[(size_t)t * NE + e] = lg[e];
    }
}

// ---------------- exclusive prefix over 8 counts ----------------
__global__ void offsets_kernel() {
    int o = 0;
    for (int e = 0; e < NE; e++) { g_offset[e] = o; o += g_count[e]; }
}

// ---------------- build compacted per-expert row lists ----------------
__global__ void assign_kernel() {
    int t = blockIdx.x * blockDim.x + threadIdx.x;
    if (t >= T) return;
    #pragma unroll
    for (int k = 0; k < 2; k++) {
        int e = g_topk_idx[t * 2 + k];
        int pos = atomicAdd(&g_cursor[e], 1);
        int g = g_offset[e] + pos;
        g_tok[g] = t;
        g_wgt[g] = g_topk_w[t * 2 + k];
    }
}

// ---------------- GEMM1: inter = silu(X @ w1^T) * (X @ w3^T), gathered rows ----
// Tile: BM=128 rows x BN=64 cols (per matrix), BK=8, 256 threads, 8x4 microtile x2.
__global__ __launch_bounds__(256)
void gemm1_kernel(const float* __restrict__ x,
                  const float* __restrict__ w1,
                  const float* __restrict__ w3) {
    int e = blockIdx.z;
    int cnt = g_count[e];
    int m0 = blockIdx.y * 128;
    if (m0 >= cnt) return;
    int n0 = blockIdx.x * 64;
    int base = g_offset[e];

    __shared__ float As[8][128];
    __shared__ float B1s[8][64];
    __shared__ float B3s[8][64];
    __shared__ int   toks[128];

    int tid = threadIdx.x;
    if (tid < 128) {
        int m = m0 + tid;
        toks[tid] = (m < cnt) ? g_tok[base + m] : -1;
    }
    __syncthreads();

    const float* W1 = w1 + (size_t)e * FF * DM;
    const float* W3 = w3 + (size_t)e * FF * DM;

    float acc1[8][4], acc3[8][4];
    #pragma unroll
    for (int i = 0; i < 8; i++)
        #pragma unroll
        for (int j = 0; j < 4; j++) { acc1[i][j] = 0.f; acc3[i][j] = 0.f; }

    int arow = tid >> 1;          // 0..127
    int ak   = (tid & 1) * 4;     // 0 or 4
    int brow = tid >> 2;          // 0..63
    int bk   = (tid & 3) * 2;     // 0,2,4,6
    int tx   = tid & 15;
    int ty   = tid >> 4;
    int atok = toks[arow];

    for (int k0 = 0; k0 < DM; k0 += 8) {
        float4 av = make_float4(0.f, 0.f, 0.f, 0.f);
        if (atok >= 0) av = *(const float4*)(x + (size_t)atok * DM + k0 + ak);
        As[ak + 0][arow] = av.x; As[ak + 1][arow] = av.y;
        As[ak + 2][arow] = av.z; As[ak + 3][arow] = av.w;

        float2 b1 = *(const float2*)(W1 + (size_t)(n0 + brow) * DM + k0 + bk);
        float2 b3 = *(const float2*)(W3 + (size_t)(n0 + brow) * DM + k0 + bk);
        B1s[bk][brow] = b1.x; B1s[bk + 1][brow] = b1.y;
        B3s[bk][brow] = b3.x; B3s[bk + 1][brow] = b3.y;
        __syncthreads();

        #pragma unroll
        for (int kk = 0; kk < 8; kk++) {
            float ar[8], b1r[4], b3r[4];
            #pragma unroll
            for (int i = 0; i < 8; i++) ar[i] = As[kk][ty * 8 + i];
            #pragma unroll
            for (int j = 0; j < 4; j++) { b1r[j] = B1s[kk][tx * 4 + j]; b3r[j] = B3s[kk][tx * 4 + j]; }
            #pragma unroll
            for (int i = 0; i < 8; i++)
                #pragma unroll
                for (int j = 0; j < 4; j++) {
                    acc1[i][j] += ar[i] * b1r[j];
                    acc3[i][j] += ar[i] * b3r[j];
                }
        }
        __syncthreads();
    }

    #pragma unroll
    for (int i = 0; i < 8; i++) {
        int m = m0 + ty * 8 + i;
        if (m < cnt) {
            size_t grow = (size_t)(base + m) * FF + n0 + tx * 4;
            #pragma unroll
            for (int j = 0; j < 4; j++) {
                float up = acc1[i][j];
                float gt = acc3[i][j];
                float sig = 1.f / (1.f + __expf(-up));
                g_inter[grow + j] = up * sig * gt;
            }
        }
    }
}

// ---------------- GEMM2: out[t] += w * (inter @ w2^T), weighted scatter-add ----
__global__ __launch_bounds__(256)
void gemm2_kernel(const float* __restrict__ w2, float* __restrict__ out) {
    int e = blockIdx.z;
    int cnt = g_count[e];
    int m0 = blockIdx.y * 128;
    if (m0 >= cnt) return;
    int n0 = blockIdx.x * 64;
    int base = g_offset[e];

    __shared__ float As[8][128];
    __shared__ float Bs[8][64];
    __shared__ int   toks[128];
    __shared__ float wgts[128];

    int tid = threadIdx.x;
    if (tid < 128) {
        int m = m0 + tid;
        bool v = (m < cnt);
        toks[tid] = v ? g_tok[base + m] : -1;
        wgts[tid] = v ? g_wgt[base + m] : 0.f;
    }
    __syncthreads();

    const float* W2 = w2 + (size_t)e * DM * FF;

    float acc[8][4];
    #pragma unroll
    for (int i = 0; i < 8; i++)
        #pragma unroll
        for (int j = 0; j < 4; j++) acc[i][j] = 0.f;

    int arow = tid >> 1;
    int ak   = (tid & 1) * 4;
    int brow = tid >> 2;
    int bk   = (tid & 3) * 2;
    int tx   = tid & 15;
    int ty   = tid >> 4;
    bool avalid = (toks[arow] >= 0);
    size_t abase = (size_t)(base + m0 + arow) * FF;

    for (int k0 = 0; k0 < FF; k0 += 8) {
        float4 av = make_float4(0.f, 0.f, 0.f, 0.f);
        if (avalid) av = *(const float4*)(g_inter + abase + k0 + ak);
        As[ak + 0][arow] = av.x; As[ak + 1][arow] = av.y;
        As[ak + 2][arow] = av.z; As[ak + 3][arow] = av.w;

        float2 bv = *(const float2*)(W2 + (size_t)(n0 + brow) * FF + k0 + bk);
        Bs[bk][brow] = bv.x; Bs[bk + 1][brow] = bv.y;
        __syncthreads();

        #pragma unroll
        for (int kk = 0; kk < 8; kk++) {
            float ar[8], br[4];
            #pragma unroll
            for (int i = 0; i < 8; i++) ar[i] = As[kk][ty * 8 + i];
            #pragma unroll
            for (int j = 0; j < 4; j++) br[j] = Bs[kk][tx * 4 + j];
            #pragma unroll
            for (int i = 0; i < 8; i++)
                #pragma unroll
                for (int j = 0; j < 4; j++) acc[i][j] += ar[i] * br[j];
        }
        __syncthreads();
    }

    #pragma unroll
    for (int i = 0; i < 8; i++) {
        int r = ty * 8 + i;
        int t = toks[r];
        if (t >= 0) {
            float w = wgts[r];
            float* op = out + (size_t)t * DM + n0 + tx * 4;
            #pragma unroll
            for (int j = 0; j < 4; j++)
                atomicAdd(op + j, w * acc[i][j]);  // exactly 2 contributions/elem -> deterministic
        }
    }
}

// ---------------- launch ----------------
extern "C" void kernel_launch(void* const* d_in, const int* in_sizes, int n_in,
                              void* d_out, int out_size) {
    const float* x  = (const float*)d_in[0];   // [T, DM]
    const float* gw = (const float*)d_in[1];   // [NE, DM]
    const float* w1 = (const float*)d_in[2];   // [NE, FF, DM]
    const float* w3 = (const float*)d_in[3];   // [NE, FF, DM]
    const float* w2 = (const float*)d_in[4];   // [NE, DM, FF]

    float* out    = (float*)d_out;             // [T, DM] then router_logits [T, NE]
    float* logits = out + (size_t)T * DM;

    cudaMemsetAsync(d_out, 0, (size_t)T * DM * sizeof(float));
    init_kernel<<<1, 32>>>();
    router_kernel<<<T, 256>>>(x, gw, logits);
    offsets_kernel<<<1, 1>>>();
    assign_kernel<<<(T + 255) / 256, 256>>>();
    gemm1_kernel<<<dim3(FF / 64, (T + 127) / 128, NE), 256>>>(x, w1, w3);
    gemm2_kernel<<<dim3(DM / 64, (T + 127) / 128, NE), 256>>>(w2, out);
}

// round 4
// speedup vs baseline: 3.1867x; 3.1867x over previous
#include <cuda_runtime.h>
#include <cstdint>
#include <math.h>

// Problem constants (fixed shapes)
#define T    2048
#define DM   1024
#define NE   8
#define FF   4096

#define KC   32            // K floats per chunk
#define PAD  36            // smem row stride in floats (32 + 4)

// ---------------- scratch (static device globals; no allocation) ----------------
__device__ int   g_count[NE];
__device__ int   g_cursor[NE];
__device__ int   g_offset[NE];
__device__ int   g_topk_idx[T * 2];
__device__ float g_topk_w[T * 2];
__device__ int   g_tok[2 * T];
__device__ float g_wgt[2 * T];
__device__ float g_inter[(size_t)(2 * T) * FF];   // 64 MB fp32 scratch

#define DEVINL __device__ __forceinline__

DEVINL uint32_t to_tf32(float f) {
    uint32_t r;
    asm("cvt.rna.tf32.f32 %0, %1;" : "=r"(r) : "f"(f));
    return r;
}

DEVINL void mma_tf32(float* d, const uint32_t* a, const uint32_t* b) {
    asm volatile(
        "mma.sync.aligned.m16n8k8.row.col.f32.tf32.tf32.f32 "
        "{%0,%1,%2,%3}, {%4,%5,%6,%7}, {%8,%9}, {%0,%1,%2,%3};"
        : "+f"(d[0]), "+f"(d[1]), "+f"(d[2]), "+f"(d[3])
        : "r"(a[0]), "r"(a[1]), "r"(a[2]), "r"(a[3]), "r"(b[0]), "r"(b[1]));
}

// ---------------- init ----------------
__global__ void init_kernel() {
    int i = threadIdx.x;
    if (i < NE) { g_count[i] = 0; g_cursor[i] = 0; }
}

// ---------------- router ----------------
__global__ void router_kernel(const float* __restrict__ x,
                              const float* __restrict__ gw,
                              float* __restrict__ logits_out) {
    int t = blockIdx.x;
    int warp = threadIdx.x >> 5;
    int lane = threadIdx.x & 31;
    const float* xr = x + (size_t)t * DM;
    const float* gr = gw + (size_t)warp * DM;
    float s = 0.f;
    for (int j = lane; j < DM; j += 32) s += xr[j] * gr[j];
    #pragma unroll
    for (int o = 16; o > 0; o >>= 1) s += __shfl_xor_sync(0xFFFFFFFFu, s, o);

    __shared__ float lg[NE];
    if (lane == 0) lg[warp] = s;
    __syncthreads();

    if (threadIdx.x == 0) {
        float mx = lg[0];
        #pragma unroll
        for (int e = 1; e < NE; e++) mx = fmaxf(mx, lg[e]);
        float p[NE];
        #pragma unroll
        for (int e = 0; e < NE; e++) p[e] = expf(lg[e] - mx);
        int i0 = 0;
        #pragma unroll
        for (int e = 1; e < NE; e++) if (p[e] > p[i0]) i0 = e;
        int i1 = -1;
        #pragma unroll
        for (int e = 0; e < NE; e++) {
            if (e == i0) continue;
            if (i1 < 0 || p[e] > p[i1]) i1 = e;
        }
        float inv = 1.f / (p[i0] + p[i1]);
        g_topk_idx[t * 2 + 0] = i0;
        g_topk_idx[t * 2 + 1] = i1;
        g_topk_w[t * 2 + 0] = p[i0] * inv;
        g_topk_w[t * 2 + 1] = p[i1] * inv;
        atomicAdd(&g_count[i0], 1);
        atomicAdd(&g_count[i1], 1);
        #pragma unroll
        for (int e = 0; e < NE; e++) logits_out[(size_t)t * NE + e] = lg[e];
    }
}

__global__ void offsets_kernel() {
    int o = 0;
    for (int e = 0; e < NE; e++) { g_offset[e] = o; o += g_count[e]; }
}

__global__ void assign_kernel() {
    int t = blockIdx.x * blockDim.x + threadIdx.x;
    if (t >= T) return;
    #pragma unroll
    for (int k = 0; k < 2; k++) {
        int e = g_topk_idx[t * 2 + k];
        int pos = atomicAdd(&g_cursor[e], 1);
        int g = g_offset[e] + pos;
        g_tok[g] = t;
        g_wgt[g] = g_topk_w[t * 2 + k];
    }
}

// smem sizing (uint32 units): toks/wgts then stage buffers of 128*PAD
#define TILE_U32 (128 * PAD)                         // 4608
#define G1_SMEM_U32 (128 + 2 * 3 * TILE_U32)         // toks + 2 stages x {A,B1,B3}
#define G2_SMEM_U32 (256 + 2 * 2 * TILE_U32)         // toks+wgts + 2 stages x {A,B}
#define G1_SMEM_BYTES (G1_SMEM_U32 * 4)
#define G2_SMEM_BYTES (G2_SMEM_U32 * 4)

// ================= GEMM1 (tf32 mma.sync): inter = silu(X w1^T) * (X w3^T) =================
__global__ __launch_bounds__(256, 1)
void gemm1_tc(const float* __restrict__ x,
              const float* __restrict__ w1,
              const float* __restrict__ w3) {
    int e = blockIdx.z;
    int cnt = g_count[e];
    int m0 = blockIdx.y * 128;
    if (m0 >= cnt) return;
    int n0 = blockIdx.x * 128;
    int base = g_offset[e];

    extern __shared__ uint32_t sm[];
    int* toks = (int*)sm;
    uint32_t* Abuf = sm + 128;                  // [2][TILE_U32]
    uint32_t* B1buf = sm + 128 + 2 * TILE_U32;  // [2][TILE_U32]
    uint32_t* B3buf = sm + 128 + 4 * TILE_U32;  // [2][TILE_U32]

    int tid = threadIdx.x;
    int wid = tid >> 5, lane = tid & 31;
    int g = lane >> 2, tq = lane & 3;
    int warpM = wid >> 2, warpN = wid & 3;

    if (tid < 128) {
        int m = m0 + tid;
        toks[tid] = (m < cnt) ? g_tok[base + m] : -1;
    }
    __syncthreads();

    const float* W1 = w1 + (size_t)e * FF * DM + (size_t)n0 * DM;
    const float* W3 = w3 + (size_t)e * FF * DM + (size_t)n0 * DM;

    float acc1[4][4][4], acc3[4][4][4];
    #pragma unroll
    for (int i = 0; i < 4; i++)
        #pragma unroll
        for (int j = 0; j < 4; j++)
            #pragma unroll
            for (int c = 0; c < 4; c++) { acc1[i][j][c] = 0.f; acc3[i][j][c] = 0.f; }

    // producer mapping: float4 f -> row f/8, col (f%8)*4 ; thread handles f = tid + p*256, p<4
    float4 ra[4], rb1[4], rb3[4];

    auto ldg_chunk = [&](int k0) {
        #pragma unroll
        for (int p = 0; p < 4; p++) {
            int f = tid + p * 256;
            int row = f >> 3, j = f & 7;
            int tk = toks[row];
            ra[p] = make_float4(0.f, 0.f, 0.f, 0.f);
            if (tk >= 0) ra[p] = *(const float4*)(x + (size_t)tk * DM + k0 + j * 4);
            rb1[p] = *(const float4*)(W1 + (size_t)row * DM + k0 + j * 4);
            rb3[p] = *(const float4*)(W3 + (size_t)row * DM + k0 + j * 4);
        }
    };
    auto sts_chunk = [&](int buf) {
        uint32_t* A  = Abuf  + buf * TILE_U32;
        uint32_t* B1 = B1buf + buf * TILE_U32;
        uint32_t* B3 = B3buf + buf * TILE_U32;
        #pragma unroll
        for (int p = 0; p < 4; p++) {
            int f = tid + p * 256;
            int row = f >> 3, j = f & 7;
            uint32_t off = row * PAD + j * 4;
            uint4 va = make_uint4(to_tf32(ra[p].x), to_tf32(ra[p].y), to_tf32(ra[p].z), to_tf32(ra[p].w));
            uint4 v1 = make_uint4(to_tf32(rb1[p].x), to_tf32(rb1[p].y), to_tf32(rb1[p].z), to_tf32(rb1[p].w));
            uint4 v3 = make_uint4(to_tf32(rb3[p].x), to_tf32(rb3[p].y), to_tf32(rb3[p].z), to_tf32(rb3[p].w));
            *(uint4*)(A + off) = va;
            *(uint4*)(B1 + off) = v1;
            *(uint4*)(B3 + off) = v3;
        }
    };
    auto compute_chunk = [&](int buf) {
        const uint32_t* A  = Abuf  + buf * TILE_U32;
        const uint32_t* B1 = B1buf + buf * TILE_U32;
        const uint32_t* B3 = B3buf + buf * TILE_U32;
        #pragma unroll
        for (int ks = 0; ks < 4; ks++) {
            int kk = ks * 8 + tq;
            uint32_t afr[4][4];
            #pragma unroll
            for (int mt = 0; mt < 4; mt++) {
                int m = warpM * 64 + mt * 16 + g;
                afr[mt][0] = A[m * PAD + kk];
                afr[mt][1] = A[(m + 8) * PAD + kk];
                afr[mt][2] = A[m * PAD + kk + 4];
                afr[mt][3] = A[(m + 8) * PAD + kk + 4];
            }
            #pragma unroll
            for (int nt = 0; nt < 4; nt++) {
                int n = warpN * 32 + nt * 8 + g;
                uint32_t b1f[2] = { B1[n * PAD + kk], B1[n * PAD + kk + 4] };
                uint32_t b3f[2] = { B3[n * PAD + kk], B3[n * PAD + kk + 4] };
                #pragma unroll
                for (int mt = 0; mt < 4; mt++) {
                    mma_tf32(acc1[mt][nt], afr[mt], b1f);
                    mma_tf32(acc3[mt][nt], afr[mt], b3f);
                }
            }
        }
    };

    const int NIT = DM / KC;   // 32
    ldg_chunk(0);
    sts_chunk(0);
    __syncthreads();
    for (int it = 0; it < NIT; ++it) {
        if (it + 1 < NIT) ldg_chunk((it + 1) * KC);
        compute_chunk(it & 1);
        if (it + 1 < NIT) sts_chunk((it + 1) & 1);
        __syncthreads();
    }

    // epilogue: silu(up) * gate -> g_inter (valid rows only)
    #pragma unroll
    for (int mt = 0; mt < 4; mt++) {
        #pragma unroll
        for (int half = 0; half < 2; half++) {
            int rl = warpM * 64 + mt * 16 + half * 8 + g;
            int m = m0 + rl;
            if (m < cnt) {
                float* orow = g_inter + (size_t)(base + m) * FF + n0;
                #pragma unroll
                for (int nt = 0; nt < 4; nt++) {
                    int col = warpN * 32 + nt * 8 + 2 * tq;
                    float u0 = acc1[mt][nt][half * 2 + 0];
                    float u1 = acc1[mt][nt][half * 2 + 1];
                    float g0 = acc3[mt][nt][half * 2 + 0];
                    float g1 = acc3[mt][nt][half * 2 + 1];
                    float2 o;
                    o.x = u0 / (1.f + __expf(-u0)) * g0;
                    o.y = u1 / (1.f + __expf(-u1)) * g1;
                    *(float2*)(orow + col) = o;
                }
            }
        }
    }
}

// ================= GEMM2 (tf32 mma.sync): out += cw * (inter w2^T) =================
__global__ __launch_bounds__(256, 1)
void gemm2_tc(const float* __restrict__ w2, float* __restrict__ out) {
    int e = blockIdx.z;
    int cnt = g_count[e];
    int m0 = blockIdx.y * 128;
    if (m0 >= cnt) return;
    int n0 = blockIdx.x * 128;
    int base = g_offset[e];

    extern __shared__ uint32_t sm[];
    int*   toks = (int*)sm;
    float* wgts = (float*)(sm + 128);
    uint32_t* Abuf = sm + 256;
    uint32_t* Bbuf = sm + 256 + 2 * TILE_U32;

    int tid = threadIdx.x;
    int wid = tid >> 5, lane = tid & 31;
    int g = lane >> 2, tq = lane & 3;
    int warpM = wid >> 2, warpN = wid & 3;

    if (tid < 128) {
        int m = m0 + tid;
        bool v = (m < cnt);
        toks[tid] = v ? g_tok[base + m] : -1;
        wgts[tid] = v ? g_wgt[base + m] : 0.f;
    }
    __syncthreads();

    const float* W2 = w2 + (size_t)e * DM * FF + (size_t)n0 * FF;
    const float* Ain = g_inter + (size_t)(base + m0) * FF;
    int mlim = cnt - m0;

    float acc[4][4][4];
    #pragma unroll
    for (int i = 0; i < 4; i++)
        #pragma unroll
        for (int j = 0; j < 4; j++)
            #pragma unroll
            for (int c = 0; c < 4; c++) acc[i][j][c] = 0.f;

    float4 ra[4], rb[4];
    auto ldg_chunk = [&](int k0) {
        #pragma unroll
        for (int p = 0; p < 4; p++) {
            int f = tid + p * 256;
            int row = f >> 3, j = f & 7;
            ra[p] = make_float4(0.f, 0.f, 0.f, 0.f);
            if (row < mlim) ra[p] = *(const float4*)(Ain + (size_t)row * FF + k0 + j * 4);
            rb[p] = *(const float4*)(W2 + (size_t)row * FF + k0 + j * 4);
        }
    };
    auto sts_chunk = [&](int buf) {
        uint32_t* A = Abuf + buf * TILE_U32;
        uint32_t* B = Bbuf + buf * TILE_U32;
        #pragma unroll
        for (int p = 0; p < 4; p++) {
            int f = tid + p * 256;
            int row = f >> 3, j = f & 7;
            uint32_t off = row * PAD + j * 4;
            *(uint4*)(A + off) = make_uint4(to_tf32(ra[p].x), to_tf32(ra[p].y), to_tf32(ra[p].z), to_tf32(ra[p].w));
            *(uint4*)(B + off) = make_uint4(to_tf32(rb[p].x), to_tf32(rb[p].y), to_tf32(rb[p].z), to_tf32(rb[p].w));
        }
    };
    auto compute_chunk = [&](int buf) {
        const uint32_t* A = Abuf + buf * TILE_U32;
        const uint32_t* B = Bbuf + buf * TILE_U32;
        #pragma unroll
        for (int ks = 0; ks < 4; ks++) {
            int kk = ks * 8 + tq;
            uint32_t afr[4][4];
            #pragma unroll
            for (int mt = 0; mt < 4; mt++) {
                int m = warpM * 64 + mt * 16 + g;
                afr[mt][0] = A[m * PAD + kk];
                afr[mt][1] = A[(m + 8) * PAD + kk];
                afr[mt][2] = A[m * PAD + kk + 4];
                afr[mt][3] = A[(m + 8) * PAD + kk + 4];
            }
            #pragma unroll
            for (int nt = 0; nt < 4; nt++) {
                int n = warpN * 32 + nt * 8 + g;
                uint32_t bf[2] = { B[n * PAD + kk], B[n * PAD + kk + 4] };
                #pragma unroll
                for (int mt = 0; mt < 4; mt++) mma_tf32(acc[mt][nt], afr[mt], bf);
            }
        }
    };

    const int NIT = FF / KC;   // 128
    ldg_chunk(0);
    sts_chunk(0);
    __syncthreads();
    for (int it = 0; it < NIT; ++it) {
        if (it + 1 < NIT) ldg_chunk((it + 1) * KC);
        compute_chunk(it & 1);
        if (it + 1 < NIT) sts_chunk((it + 1) & 1);
        __syncthreads();
    }

    // epilogue: weighted deterministic scatter-add (2 contributions per element)
    #pragma unroll
    for (int mt = 0; mt < 4; mt++) {
        #pragma unroll
        for (int half = 0; half < 2; half++) {
            int rl = warpM * 64 + mt * 16 + half * 8 + g;
            int t = toks[rl];
            if (t >= 0) {
                float w = wgts[rl];
                float* orow = out + (size_t)t * DM + n0;
                #pragma unroll
                for (int nt = 0; nt < 4; nt++) {
                    int col = warpN * 32 + nt * 8 + 2 * tq;
                    atomicAdd(orow + col,     w * acc[mt][nt][half * 2 + 0]);
                    atomicAdd(orow + col + 1, w * acc[mt][nt][half * 2 + 1]);
                }
            }
        }
    }
}

// ---------------- launch ----------------
extern "C" void kernel_launch(void* const* d_in, const int* in_sizes, int n_in,
                              void* d_out, int out_size) {
    const float* x  = (const float*)d_in[0];   // [T, DM]
    const float* gw = (const float*)d_in[1];   // [NE, DM]
    const float* w1 = (const float*)d_in[2];   // [NE, FF, DM]
    const float* w3 = (const float*)d_in[3];   // [NE, FF, DM]
    const float* w2 = (const float*)d_in[4];   // [NE, DM, FF]

    float* out    = (float*)d_out;             // [T, DM] then router_logits [T, NE]
    float* logits = out + (size_t)T * DM;

    cudaFuncSetAttribute(gemm1_tc, cudaFuncAttributeMaxDynamicSharedMemorySize, G1_SMEM_BYTES);
    cudaFuncSetAttribute(gemm2_tc, cudaFuncAttributeMaxDynamicSharedMemorySize, G2_SMEM_BYTES);

    cudaMemsetAsync(d_out, 0, (size_t)T * DM * sizeof(float));
    init_kernel<<<1, 32>>>();
    router_kernel<<<T, 256>>>(x, gw, logits);
    offsets_kernel<<<1, 1>>>();
    assign_kernel<<<(T + 255) / 256, 256>>>();
    gemm1_tc<<<dim3(FF / 128, (2 * T) / 128, NE), 256, G1_SMEM_BYTES>>>(x, w1, w3);
    gemm2_tc<<<dim3(DM / 128, (2 * T) / 128, NE), 256, G2_SMEM_BYTES>>>(w2, out);
}

// round 5
// speedup vs baseline: 3.3320x; 1.0456x over previous
#include <cuda_runtime.h>
#include <cstdint>
#include <math.h>

// Problem constants (fixed shapes)
#define T    2048
#define DM   1024
#define NE   8
#define FF   4096

#define KC   32            // K floats per chunk
#define PAD  36            // smem row stride in floats (32 + 4)

// ---------------- scratch (static device globals; no allocation) ----------------
__device__ int   g_count[NE];
__device__ int   g_cursor[NE];
__device__ int   g_offset[NE];
__device__ int   g_topk_idx[T * 2];
__device__ float g_topk_w[T * 2];
__device__ int   g_tok[2 * T];
__device__ float g_wgt[2 * T];
__device__ float g_inter[(size_t)(2 * T) * FF];   // 64 MB fp32 scratch

#define DEVINL __device__ __forceinline__

DEVINL uint32_t to_tf32(float f) {
    uint32_t r;
    asm("cvt.rna.tf32.f32 %0, %1;" : "=r"(r) : "f"(f));
    return r;
}
DEVINL uint4 to_tf32_v4(float4 v) {
    return make_uint4(to_tf32(v.x), to_tf32(v.y), to_tf32(v.z), to_tf32(v.w));
}

DEVINL void mma_tf32(float* d, const uint32_t* a, const uint32_t* b) {
    asm volatile(
        "mma.sync.aligned.m16n8k8.row.col.f32.tf32.tf32.f32 "
        "{%0,%1,%2,%3}, {%4,%5,%6,%7}, {%8,%9}, {%0,%1,%2,%3};"
        : "+f"(d[0]), "+f"(d[1]), "+f"(d[2]), "+f"(d[3])
        : "r"(a[0]), "r"(a[1]), "r"(a[2]), "r"(a[3]), "r"(b[0]), "r"(b[1]));
}

// ---------------- init ----------------
__global__ void init_kernel() {
    int i = threadIdx.x;
    if (i < NE) { g_count[i] = 0; g_cursor[i] = 0; }
}

// ---------------- router ----------------
__global__ void router_kernel(const float* __restrict__ x,
                              const float* __restrict__ gw,
                              float* __restrict__ logits_out) {
    int t = blockIdx.x;
    int warp = threadIdx.x >> 5;
    int lane = threadIdx.x & 31;
    const float* xr = x + (size_t)t * DM;
    const float* gr = gw + (size_t)warp * DM;
    float s = 0.f;
    for (int j = lane; j < DM; j += 32) s += xr[j] * gr[j];
    #pragma unroll
    for (int o = 16; o > 0; o >>= 1) s += __shfl_xor_sync(0xFFFFFFFFu, s, o);

    __shared__ float lg[NE];
    if (lane == 0) lg[warp] = s;
    __syncthreads();

    if (threadIdx.x == 0) {
        float mx = lg[0];
        #pragma unroll
        for (int e = 1; e < NE; e++) mx = fmaxf(mx, lg[e]);
        float p[NE];
        #pragma unroll
        for (int e = 0; e < NE; e++) p[e] = expf(lg[e] - mx);
        int i0 = 0;
        #pragma unroll
        for (int e = 1; e < NE; e++) if (p[e] > p[i0]) i0 = e;
        int i1 = -1;
        #pragma unroll
        for (int e = 0; e < NE; e++) {
            if (e == i0) continue;
            if (i1 < 0 || p[e] > p[i1]) i1 = e;
        }
        float inv = 1.f / (p[i0] + p[i1]);
        g_topk_idx[t * 2 + 0] = i0;
        g_topk_idx[t * 2 + 1] = i1;
        g_topk_w[t * 2 + 0] = p[i0] * inv;
        g_topk_w[t * 2 + 1] = p[i1] * inv;
        atomicAdd(&g_count[i0], 1);
        atomicAdd(&g_count[i1], 1);
        #pragma unroll
        for (int e = 0; e < NE; e++) logits_out[(size_t)t * NE + e] = lg[e];
    }
}

// ---------------- offsets + assignment (single block) ----------------
__global__ void assign_kernel() {
    if (threadIdx.x == 0) {
        int o = 0;
        #pragma unroll
        for (int e = 0; e < NE; e++) { g_offset[e] = o; o += g_count[e]; }
    }
    __syncthreads();
    for (int t = threadIdx.x; t < T; t += blockDim.x) {
        #pragma unroll
        for (int k = 0; k < 2; k++) {
            int e = g_topk_idx[t * 2 + k];
            int pos = atomicAdd(&g_cursor[e], 1);
            int g = g_offset[e] + pos;
            g_tok[g] = t;
            g_wgt[g] = g_topk_w[t * 2 + k];
        }
    }
}

// smem sizing (uint32 units)
#define TILE128_U32 (128 * PAD)                      // 4608
#define TILE256_U32 (256 * PAD)                      // 9216
#define G1_SMEM_U32 (128 + 2 * 3 * TILE128_U32)      // toks + 2 stages x {A,B1,B3}
#define G2_SMEM_U32 (512 + 2 * (TILE256_U32 + TILE128_U32)) // toks+wgts + 2 stages x {A256,B128}
#define G1_SMEM_BYTES (G1_SMEM_U32 * 4)
#define G2_SMEM_BYTES (G2_SMEM_U32 * 4)

// ================= GEMM1 (tf32 mma.sync): inter = silu(X w1^T) * (X w3^T) =================
// 512 threads, block 128x128, warp tile 32x32 (mt=2, nt=4), 16 warps.
__global__ __launch_bounds__(512, 1)
void gemm1_tc(const float* __restrict__ x,
              const float* __restrict__ w1,
              const float* __restrict__ w3) {
    int e = blockIdx.z;
    int cnt = g_count[e];
    int m0 = blockIdx.y * 128;
    if (m0 >= cnt) return;
    int n0 = blockIdx.x * 128;
    int base = g_offset[e];

    extern __shared__ uint32_t sm[];
    int* toks = (int*)sm;
    uint32_t* Abuf  = sm + 128;
    uint32_t* B1buf = sm + 128 + 2 * TILE128_U32;
    uint32_t* B3buf = sm + 128 + 4 * TILE128_U32;

    int tid = threadIdx.x;
    int wid = tid >> 5, lane = tid & 31;
    int g = lane >> 2, tq = lane & 3;
    int warpM = wid >> 2, warpN = wid & 3;   // 4x4 warps

    if (tid < 128) {
        int m = m0 + tid;
        toks[tid] = (m < cnt) ? g_tok[base + m] : -1;
    }
    __syncthreads();

    const float* W1 = w1 + (size_t)e * FF * DM + (size_t)n0 * DM;
    const float* W3 = w3 + (size_t)e * FF * DM + (size_t)n0 * DM;

    float acc1[2][4][4], acc3[2][4][4];
    #pragma unroll
    for (int i = 0; i < 2; i++)
        #pragma unroll
        for (int j = 0; j < 4; j++)
            #pragma unroll
            for (int c = 0; c < 4; c++) { acc1[i][j][c] = 0.f; acc3[i][j][c] = 0.f; }

    // producers: 1024 float4 per tile, 512 threads -> 2 per thread
    float4 ra[2], rb1[2], rb3[2];

    auto ldg_chunk = [&](int k0) {
        #pragma unroll
        for (int p = 0; p < 2; p++) {
            int f = tid + p * 512;
            int row = f >> 3, j = f & 7;
            int tk = toks[row];
            ra[p] = make_float4(0.f, 0.f, 0.f, 0.f);
            if (tk >= 0) ra[p] = *(const float4*)(x + (size_t)tk * DM + k0 + j * 4);
            rb1[p] = *(const float4*)(W1 + (size_t)row * DM + k0 + j * 4);
            rb3[p] = *(const float4*)(W3 + (size_t)row * DM + k0 + j * 4);
        }
    };
    auto sts_chunk = [&](int buf) {
        uint32_t* A  = Abuf  + buf * TILE128_U32;
        uint32_t* B1 = B1buf + buf * TILE128_U32;
        uint32_t* B3 = B3buf + buf * TILE128_U32;
        #pragma unroll
        for (int p = 0; p < 2; p++) {
            int f = tid + p * 512;
            int row = f >> 3, j = f & 7;
            uint32_t off = row * PAD + j * 4;
            *(uint4*)(A + off)  = to_tf32_v4(ra[p]);
            *(uint4*)(B1 + off) = to_tf32_v4(rb1[p]);
            *(uint4*)(B3 + off) = to_tf32_v4(rb3[p]);
        }
    };
    auto compute_chunk = [&](int buf) {
        const uint32_t* A  = Abuf  + buf * TILE128_U32;
        const uint32_t* B1 = B1buf + buf * TILE128_U32;
        const uint32_t* B3 = B3buf + buf * TILE128_U32;
        #pragma unroll
        for (int ks = 0; ks < 4; ks++) {
            int kk = ks * 8 + tq;
            uint32_t afr[2][4];
            #pragma unroll
            for (int mt = 0; mt < 2; mt++) {
                int m = warpM * 32 + mt * 16 + g;
                afr[mt][0] = A[m * PAD + kk];
                afr[mt][1] = A[(m + 8) * PAD + kk];
                afr[mt][2] = A[m * PAD + kk + 4];
                afr[mt][3] = A[(m + 8) * PAD + kk + 4];
            }
            #pragma unroll
            for (int nt = 0; nt < 4; nt++) {
                int n = warpN * 32 + nt * 8 + g;
                uint32_t b1f[2] = { B1[n * PAD + kk], B1[n * PAD + kk + 4] };
                uint32_t b3f[2] = { B3[n * PAD + kk], B3[n * PAD + kk + 4] };
                #pragma unroll
                for (int mt = 0; mt < 2; mt++) {
                    mma_tf32(acc1[mt][nt], afr[mt], b1f);
                    mma_tf32(acc3[mt][nt], afr[mt], b3f);
                }
            }
        }
    };

    const int NIT = DM / KC;   // 32
    ldg_chunk(0);
    sts_chunk(0);
    __syncthreads();
    for (int it = 0; it < NIT; ++it) {
        if (it + 1 < NIT) ldg_chunk((it + 1) * KC);
        compute_chunk(it & 1);
        if (it + 1 < NIT) sts_chunk((it + 1) & 1);
        __syncthreads();
    }

    // epilogue: silu(up) * gate -> g_inter (valid rows only)
    #pragma unroll
    for (int mt = 0; mt < 2; mt++) {
        #pragma unroll
        for (int half = 0; half < 2; half++) {
            int rl = warpM * 32 + mt * 16 + half * 8 + g;
            int m = m0 + rl;
            if (m < cnt) {
                float* orow = g_inter + (size_t)(base + m) * FF + n0;
                #pragma unroll
                for (int nt = 0; nt < 4; nt++) {
                    int col = warpN * 32 + nt * 8 + 2 * tq;
                    float u0 = acc1[mt][nt][half * 2 + 0];
                    float u1 = acc1[mt][nt][half * 2 + 1];
                    float g0 = acc3[mt][nt][half * 2 + 0];
                    float g1 = acc3[mt][nt][half * 2 + 1];
                    float2 o;
                    o.x = u0 / (1.f + __expf(-u0)) * g0;
                    o.y = u1 / (1.f + __expf(-u1)) * g1;
                    *(float2*)(orow + col) = o;
                }
            }
        }
    }
}

// ================= GEMM2 (tf32 mma.sync): out += cw * (inter w2^T) =================
// 512 threads, block 256x128, warp tile 64x32 (mt=4, nt=4), 16 warps.
__global__ __launch_bounds__(512, 1)
void gemm2_tc(const float* __restrict__ w2, float* __restrict__ out) {
    int e = blockIdx.z;
    int cnt = g_count[e];
    int m0 = blockIdx.y * 256;
    if (m0 >= cnt) return;
    int n0 = blockIdx.x * 128;
    int base = g_offset[e];

    extern __shared__ uint32_t sm[];
    int*   toks = (int*)sm;                 // [256]
    float* wgts = (float*)(sm + 256);       // [256]
    uint32_t* Abuf = sm + 512;                            // 2 x TILE256
    uint32_t* Bbuf = sm + 512 + 2 * TILE256_U32;          // 2 x TILE128

    int tid = threadIdx.x;
    int wid = tid >> 5, lane = tid & 31;
    int g = lane >> 2, tq = lane & 3;
    int warpM = wid >> 2, warpN = wid & 3;   // 4(M) x 4(N) warps

    if (tid < 256) {
        int m = m0 + tid;
        bool v = (m < cnt);
        toks[tid] = v ? g_tok[base + m] : -1;
        wgts[tid] = v ? g_wgt[base + m] : 0.f;
    }
    __syncthreads();

    const float* W2 = w2 + (size_t)e * DM * FF + (size_t)n0 * FF;
    const float* Ain = g_inter + (size_t)(base + m0) * FF;
    int mlim = cnt - m0;

    float acc[4][4][4];
    #pragma unroll
    for (int i = 0; i < 4; i++)
        #pragma unroll
        for (int j = 0; j < 4; j++)
            #pragma unroll
            for (int c = 0; c < 4; c++) acc[i][j][c] = 0.f;

    float4 ra[4], rb[2];
    auto ldg_chunk = [&](int k0) {
        #pragma unroll
        for (int p = 0; p < 4; p++) {               // A: 2048 f4 / 512 thr
            int f = tid + p * 512;
            int row = f >> 3, j = f & 7;
            ra[p] = make_float4(0.f, 0.f, 0.f, 0.f);
            if (row < mlim) ra[p] = *(const float4*)(Ain + (size_t)row * FF + k0 + j * 4);
        }
        #pragma unroll
        for (int p = 0; p < 2; p++) {               // B: 1024 f4 / 512 thr
            int f = tid + p * 512;
            int row = f >> 3, j = f & 7;
            rb[p] = *(const float4*)(W2 + (size_t)row * FF + k0 + j * 4);
        }
    };
    auto sts_chunk = [&](int buf) {
        uint32_t* A = Abuf + buf * TILE256_U32;
        uint32_t* B = Bbuf + buf * TILE128_U32;
        #pragma unroll
        for (int p = 0; p < 4; p++) {
            int f = tid + p * 512;
            int row = f >> 3, j = f & 7;
            *(uint4*)(A + row * PAD + j * 4) = to_tf32_v4(ra[p]);
        }
        #pragma unroll
        for (int p = 0; p < 2; p++) {
            int f = tid + p * 512;
            int row = f >> 3, j = f & 7;
            *(uint4*)(B + row * PAD + j * 4) = to_tf32_v4(rb[p]);
        }
    };
    auto compute_chunk = [&](int buf) {
        const uint32_t* A = Abuf + buf * TILE256_U32;
        const uint32_t* B = Bbuf + buf * TILE128_U32;
        #pragma unroll
        for (int ks = 0; ks < 4; ks++) {
            int kk = ks * 8 + tq;
            uint32_t afr[4][4];
            #pragma unroll
            for (int mt = 0; mt < 4; mt++) {
                int m = warpM * 64 + mt * 16 + g;
                afr[mt][0] = A[m * PAD + kk];
                afr[mt][1] = A[(m + 8) * PAD + kk];
                afr[mt][2] = A[m * PAD + kk + 4];
                afr[mt][3] = A[(m + 8) * PAD + kk + 4];
            }
            #pragma unroll
            for (int nt = 0; nt < 4; nt++) {
                int n = warpN * 32 + nt * 8 + g;
                uint32_t bf[2] = { B[n * PAD + kk], B[n * PAD + kk + 4] };
                #pragma unroll
                for (int mt = 0; mt < 4; mt++) mma_tf32(acc[mt][nt], afr[mt], bf);
            }
        }
    };

    const int NIT = FF / KC;   // 128
    ldg_chunk(0);
    sts_chunk(0);
    __syncthreads();
    for (int it = 0; it < NIT; ++it) {
        if (it + 1 < NIT) ldg_chunk((it + 1) * KC);
        compute_chunk(it & 1);
        if (it + 1 < NIT) sts_chunk((it + 1) & 1);
        __syncthreads();
    }

    // epilogue: weighted deterministic scatter-add (2 contributions per element)
    #pragma unroll
    for (int mt = 0; mt < 4; mt++) {
        #pragma unroll
        for (int half = 0; half < 2; half++) {
            int rl = warpM * 64 + mt * 16 + half * 8 + g;
            int t = toks[rl];
            if (t >= 0) {
                float w = wgts[rl];
                float* orow = out + (size_t)t * DM + n0;
                #pragma unroll
                for (int nt = 0; nt < 4; nt++) {
                    int col = warpN * 32 + nt * 8 + 2 * tq;
                    atomicAdd(orow + col,     w * acc[mt][nt][half * 2 + 0]);
                    atomicAdd(orow + col + 1, w * acc[mt][nt][half * 2 + 1]);
                }
            }
        }
    }
}

// ---------------- launch ----------------
extern "C" void kernel_launch(void* const* d_in, const int* in_sizes, int n_in,
                              void* d_out, int out_size) {
    const float* x  = (const float*)d_in[0];   // [T, DM]
    const float* gw = (const float*)d_in[1];   // [NE, DM]
    const float* w1 = (const float*)d_in[2];   // [NE, FF, DM]
    const float* w3 = (const float*)d_in[3];   // [NE, FF, DM]
    const float* w2 = (const float*)d_in[4];   // [NE, DM, FF]

    float* out    = (float*)d_out;             // [T, DM] then router_logits [T, NE]
    float* logits = out + (size_t)T * DM;

    cudaFuncSetAttribute(gemm1_tc, cudaFuncAttributeMaxDynamicSharedMemorySize, G1_SMEM_BYTES);
    cudaFuncSetAttribute(gemm2_tc, cudaFuncAttributeMaxDynamicSharedMemorySize, G2_SMEM_BYTES);

    cudaMemsetAsync(d_out, 0, (size_t)T * DM * sizeof(float));
    init_kernel<<<1, 32>>>();
    router_kernel<<<T, 256>>>(x, gw, logits);
    assign_kernel<<<1, 256>>>();
    gemm1_tc<<<dim3(FF / 128, (2 * T) / 128, NE), 512, G1_SMEM_BYTES>>>(x, w1, w3);
    gemm2_tc<<<dim3(DM / 128, (2 * T) / 256, NE), 512, G2_SMEM_BYTES>>>(w2, out);
}